// round 7
// baseline (speedup 1.0000x reference)
#include <cuda_runtime.h>

#define NSETS 8
#define NPTS  4096
#define DF    16
#define KK    16
#define QT    128   // queries per block == threads per block
#define CT    128   // candidate tile size
#define NTILES (NPTS / CT)

// dot of two 16-float vectors held as 4x float4, 4-way partial sums.
// Used for BOTH norms and cross dots so that self-distance cancels exactly.
__device__ __forceinline__ float dot16(const float4& a0, const float4& a1,
                                       const float4& a2, const float4& a3,
                                       const float4& b0, const float4& b1,
                                       const float4& b2, const float4& b3) {
    float s0 = a0.x * b0.x;
    s0 = fmaf(a0.y, b0.y, s0);
    s0 = fmaf(a0.z, b0.z, s0);
    s0 = fmaf(a0.w, b0.w, s0);
    float s1 = a1.x * b1.x;
    s1 = fmaf(a1.y, b1.y, s1);
    s1 = fmaf(a1.z, b1.z, s1);
    s1 = fmaf(a1.w, b1.w, s1);
    float s2 = a2.x * b2.x;
    s2 = fmaf(a2.y, b2.y, s2);
    s2 = fmaf(a2.z, b2.z, s2);
    s2 = fmaf(a2.w, b2.w, s2);
    float s3 = a3.x * b3.x;
    s3 = fmaf(a3.y, b3.y, s3);
    s3 = fmaf(a3.z, b3.z, s3);
    s3 = fmaf(a3.w, b3.w, s3);
    return (s0 + s1) + (s2 + s3);
}

__global__ __launch_bounds__(QT) void knn_kernel(const float* __restrict__ x,
                                                 float* __restrict__ out) {
    __shared__ float4 sC[CT * 4];  // candidate tile, 4 float4 per point
    __shared__ float  sN[CT];      // candidate squared norms

    const int set = blockIdx.y;
    const int qi  = blockIdx.x * QT + threadIdx.x;   // query index within set
    const float* xs = x + (size_t)set * NPTS * DF;

    // ---- load query point into registers + its norm ----
    const float4* qp = reinterpret_cast<const float4*>(xs + (size_t)qi * DF);
    const float4 q0 = qp[0], q1 = qp[1], q2 = qp[2], q3 = qp[3];
    const float qn = dot16(q0, q1, q2, q3, q0, q1, q2, q3);

    // ---- register-resident sorted top-k (ascending distance) ----
    float bestD[KK];
    int   bestI[KK];
#pragma unroll
    for (int t = 0; t < KK; ++t) {
        bestD[t] = __int_as_float(0x7f800000);  // +inf
        bestI[t] = 0;
    }

    for (int tile = 0; tile < NTILES; ++tile) {
        __syncthreads();
        // stage candidate tile: thread t loads point (tile*CT + t)
        {
            const float4* cp = reinterpret_cast<const float4*>(
                xs + (size_t)(tile * CT + threadIdx.x) * DF);
            const float4 a0 = cp[0], a1 = cp[1], a2 = cp[2], a3 = cp[3];
            sC[threadIdx.x * 4 + 0] = a0;
            sC[threadIdx.x * 4 + 1] = a1;
            sC[threadIdx.x * 4 + 2] = a2;
            sC[threadIdx.x * 4 + 3] = a3;
            sN[threadIdx.x] = dot16(a0, a1, a2, a3, a0, a1, a2, a3);
        }
        __syncthreads();

#pragma unroll 2
        for (int j = 0; j < CT; ++j) {
            const float4 c0 = sC[j * 4 + 0];
            const float4 c1 = sC[j * 4 + 1];
            const float4 c2 = sC[j * 4 + 2];
            const float4 c3 = sC[j * 4 + 3];
            const float dot = dot16(q0, q1, q2, q3, c0, c1, c2, c3);
            // reference order: (||q||^2 + ||c||^2) - 2*dot
            const float d = fmaf(-2.0f, dot, qn + sN[j]);

            if (d < bestD[KK - 1]) {
                const int idx = tile * CT + j;
                // predicated sorted insert (stable: ties keep lower index)
#pragma unroll
                for (int t = KK - 1; t >= 1; --t) {
                    const bool shift = d < bestD[t - 1];
                    const bool here  = d < bestD[t];
                    const float nd = shift ? bestD[t - 1] : (here ? d : bestD[t]);
                    const int   ni = shift ? bestI[t - 1] : (here ? idx : bestI[t]);
                    bestD[t] = nd;
                    bestI[t] = ni;
                }
                if (d < bestD[0]) { bestD[0] = d; bestI[0] = idx; }
            }
        }
    }

    // ---- write outputs: [src | dst | dist], each (NSETS*NPTS*KK) floats ----
    const int g    = set * NPTS + qi;          // global node id (also src value)
    const int base = set * NPTS;               // per-set node-id offset
    const size_t stride = (size_t)NSETS * NPTS * KK;

    float4* o_src = reinterpret_cast<float4*>(out + (size_t)g * KK);
    float4* o_dst = reinterpret_cast<float4*>(out + stride + (size_t)g * KK);
    float4* o_dis = reinterpret_cast<float4*>(out + 2 * stride + (size_t)g * KK);

    const float sv = (float)g;
#pragma unroll
    for (int t = 0; t < KK; t += 4) {
        o_src[t / 4] = make_float4(sv, sv, sv, sv);
        o_dst[t / 4] = make_float4((float)(base + bestI[t + 0]),
                                   (float)(base + bestI[t + 1]),
                                   (float)(base + bestI[t + 2]),
                                   (float)(base + bestI[t + 3]));
        o_dis[t / 4] = make_float4(bestD[t + 0], bestD[t + 1],
                                   bestD[t + 2], bestD[t + 3]);
    }
}

extern "C" void kernel_launch(void* const* d_in, const int* in_sizes, int n_in,
                              void* d_out, int out_size) {
    const float* x = (const float*)d_in[0];
    float* out = (float*)d_out;
    dim3 grid(NPTS / QT, NSETS);
    knn_kernel<<<grid, QT>>>(x, out);
}

// round 8
// speedup vs baseline: 1.0329x; 1.0329x over previous
#include <cuda_runtime.h>

#define NSETS 8
#define NPTS  4096
#define DF    16
#define KK    16
#define QT    128                 // queries per block == threads per block
#define CT    128                 // candidate tile size
#define SPLIT 4                   // candidate-range splits (occupancy lever)
#define CPS   (NPTS / SPLIT)      // candidates per split = 1024
#define NQ    (NSETS * NPTS)      // total queries = 32768

typedef unsigned long long u64;

// ---- device scratch for partial top-k (no allocs allowed) ----
__device__ float g_partD[NQ * SPLIT * KK];
__device__ int   g_partI[NQ * SPLIT * KK];

// ---- packed f32x2 helpers (two fp32 lanes per instruction, exact) ----
__device__ __forceinline__ u64 f2mul(u64 a, u64 b) {
    u64 d; asm("mul.rn.f32x2 %0, %1, %2;" : "=l"(d) : "l"(a), "l"(b)); return d;
}
__device__ __forceinline__ u64 f2fma(u64 a, u64 b, u64 c) {
    u64 d; asm("fma.rn.f32x2 %0, %1, %2, %3;" : "=l"(d) : "l"(a), "l"(b), "l"(c)); return d;
}
__device__ __forceinline__ u64 f2add(u64 a, u64 b) {
    u64 d; asm("add.rn.f32x2 %0, %1, %2;" : "=l"(d) : "l"(a), "l"(b)); return d;
}

// 16-dim dot with a FIXED summation tree, used for norms AND cross dots so
// that self-distance cancels exactly: dot(q,q)==qn ⇒ fmaf(-2,dot,qn+cn)==0.
__device__ __forceinline__ float pdot16(const u64* a, const u64* b) {
    u64 pA = f2mul(a[0], b[0]);
    pA = f2fma(a[1], b[1], pA);
    pA = f2fma(a[2], b[2], pA);
    pA = f2fma(a[3], b[3], pA);
    u64 pB = f2mul(a[4], b[4]);
    pB = f2fma(a[5], b[5], pB);
    pB = f2fma(a[6], b[6], pB);
    pB = f2fma(a[7], b[7], pB);
    u64 pC = f2add(pA, pB);
    float lo, hi;
    asm("mov.b64 {%0, %1}, %2;" : "=f"(lo), "=f"(hi) : "l"(pC));
    return lo + hi;
}

// ============================ pass 1: partial top-k ============================
__global__ __launch_bounds__(QT) void knn_part(const float* __restrict__ x) {
    __shared__ ulonglong2 sC[CT * 4];  // candidate tile: 4x ulonglong2 per point
    __shared__ float      sN[CT];      // candidate squared norms

    const int set   = blockIdx.y;
    const int split = blockIdx.z;
    const int qi    = blockIdx.x * QT + threadIdx.x;
    const float* xs = x + (size_t)set * NPTS * DF;

    // query point (packed) + its norm
    u64 q[8];
    {
        const ulonglong2* qp = reinterpret_cast<const ulonglong2*>(xs + (size_t)qi * DF);
        ulonglong2 w0 = qp[0], w1 = qp[1], w2 = qp[2], w3 = qp[3];
        q[0] = w0.x; q[1] = w0.y; q[2] = w1.x; q[3] = w1.y;
        q[4] = w2.x; q[5] = w2.y; q[6] = w3.x; q[7] = w3.y;
    }
    const float qn = pdot16(q, q);

    float bestD[KK];
    int   bestI[KK];
#pragma unroll
    for (int t = 0; t < KK; ++t) {
        bestD[t] = __int_as_float(0x7f800000);  // +inf
        bestI[t] = 0;
    }

    const int cbase = split * CPS;
    for (int tile = 0; tile < CPS / CT; ++tile) {
        const int cj0 = cbase + tile * CT;
        __syncthreads();
        {
            const ulonglong2* cp = reinterpret_cast<const ulonglong2*>(
                xs + (size_t)(cj0 + threadIdx.x) * DF);
            ulonglong2 w0 = cp[0], w1 = cp[1], w2 = cp[2], w3 = cp[3];
            sC[threadIdx.x * 4 + 0] = w0;
            sC[threadIdx.x * 4 + 1] = w1;
            sC[threadIdx.x * 4 + 2] = w2;
            sC[threadIdx.x * 4 + 3] = w3;
            u64 a[8] = {w0.x, w0.y, w1.x, w1.y, w2.x, w2.y, w3.x, w3.y};
            sN[threadIdx.x] = pdot16(a, a);
        }
        __syncthreads();

#pragma unroll 4
        for (int j = 0; j < CT; ++j) {
            const ulonglong2* sp = &sC[j * 4];
            ulonglong2 w0 = sp[0], w1 = sp[1], w2 = sp[2], w3 = sp[3];
            u64 c[8] = {w0.x, w0.y, w1.x, w1.y, w2.x, w2.y, w3.x, w3.y};
            const float dot = pdot16(q, c);
            const float d = fmaf(-2.0f, dot, qn + sN[j]);

            if (d < bestD[KK - 1]) {
                const int idx = cj0 + j;
#pragma unroll
                for (int t = KK - 1; t >= 1; --t) {
                    const bool shift = d < bestD[t - 1];
                    const bool here  = d < bestD[t];
                    bestD[t] = shift ? bestD[t - 1] : (here ? d : bestD[t]);
                    bestI[t] = shift ? bestI[t - 1] : (here ? idx : bestI[t]);
                }
                if (d < bestD[0]) { bestD[0] = d; bestI[0] = idx; }
            }
        }
    }

    // write sorted partial list
    const int q_glob = set * NPTS + qi;
    float4* pd = reinterpret_cast<float4*>(&g_partD[((size_t)q_glob * SPLIT + split) * KK]);
    int4*   pi = reinterpret_cast<int4*>(&g_partI[((size_t)q_glob * SPLIT + split) * KK]);
#pragma unroll
    for (int t = 0; t < KK; t += 4) {
        pd[t / 4] = make_float4(bestD[t], bestD[t + 1], bestD[t + 2], bestD[t + 3]);
        pi[t / 4] = make_int4(bestI[t], bestI[t + 1], bestI[t + 2], bestI[t + 3]);
    }
}

// ============================ pass 2: merge + emit ============================
__device__ __forceinline__ bool lex_less(float d1, int i1, float d2, int i2) {
    return (d1 < d2) || (d1 == d2 && i1 < i2);
}

// merge two sorted-ascending 16-lists, keep the 16 smallest, result sorted.
__device__ __forceinline__ void merge16(const float* dA, const int* iA,
                                        const float* dB, const int* iB,
                                        float* dR, int* iR) {
    // min(A[i], B[15-i]) = the 16 smallest, as a bitonic sequence
#pragma unroll
    for (int i = 0; i < KK; ++i) {
        const bool ta = lex_less(dA[i], iA[i], dB[KK - 1 - i], iB[KK - 1 - i]);
        dR[i] = ta ? dA[i] : dB[KK - 1 - i];
        iR[i] = ta ? iA[i] : iB[KK - 1 - i];
    }
    // bitonic merge network: strides 8,4,2,1
#pragma unroll
    for (int s = 8; s >= 1; s >>= 1) {
#pragma unroll
        for (int i = 0; i < KK; ++i) {
            if ((i & s) == 0) {
                const bool swap = !lex_less(dR[i], iR[i], dR[i + s], iR[i + s]);
                const float td = swap ? dR[i + s] : dR[i];
                const int   ti = swap ? iR[i + s] : iR[i];
                dR[i + s] = swap ? dR[i] : dR[i + s];
                iR[i + s] = swap ? iR[i] : iR[i + s];
                dR[i] = td;
                iR[i] = ti;
            }
        }
    }
}

__global__ __launch_bounds__(128) void knn_merge(float* __restrict__ out) {
    const int q = blockIdx.x * 128 + threadIdx.x;  // global query id
    if (q >= NQ) return;

    float D[SPLIT][KK];
    int   I[SPLIT][KK];
#pragma unroll
    for (int s = 0; s < SPLIT; ++s) {
        const float4* pd = reinterpret_cast<const float4*>(&g_partD[((size_t)q * SPLIT + s) * KK]);
        const int4*   pi = reinterpret_cast<const int4*>(&g_partI[((size_t)q * SPLIT + s) * KK]);
#pragma unroll
        for (int t = 0; t < KK / 4; ++t) {
            float4 v = pd[t];
            int4   w = pi[t];
            D[s][t * 4 + 0] = v.x; D[s][t * 4 + 1] = v.y;
            D[s][t * 4 + 2] = v.z; D[s][t * 4 + 3] = v.w;
            I[s][t * 4 + 0] = w.x; I[s][t * 4 + 1] = w.y;
            I[s][t * 4 + 2] = w.z; I[s][t * 4 + 3] = w.w;
        }
    }

    float m01[KK], m23[KK], fin[KK];
    int   j01[KK], j23[KK], jin[KK];
    merge16(D[0], I[0], D[1], I[1], m01, j01);
    merge16(D[2], I[2], D[3], I[3], m23, j23);
    merge16(m01, j01, m23, j23, fin, jin);

    // emit [src | dst | dist], each NQ*KK floats
    const int set  = q / NPTS;
    const int base = set * NPTS;
    const size_t stride = (size_t)NQ * KK;

    float4* o_src = reinterpret_cast<float4*>(out + (size_t)q * KK);
    float4* o_dst = reinterpret_cast<float4*>(out + stride + (size_t)q * KK);
    float4* o_dis = reinterpret_cast<float4*>(out + 2 * stride + (size_t)q * KK);

    const float sv = (float)q;
#pragma unroll
    for (int t = 0; t < KK; t += 4) {
        o_src[t / 4] = make_float4(sv, sv, sv, sv);
        o_dst[t / 4] = make_float4((float)(base + jin[t + 0]),
                                   (float)(base + jin[t + 1]),
                                   (float)(base + jin[t + 2]),
                                   (float)(base + jin[t + 3]));
        o_dis[t / 4] = make_float4(fin[t + 0], fin[t + 1], fin[t + 2], fin[t + 3]);
    }
}

extern "C" void kernel_launch(void* const* d_in, const int* in_sizes, int n_in,
                              void* d_out, int out_size) {
    const float* x = (const float*)d_in[0];
    float* out = (float*)d_out;

    dim3 grid1(NPTS / QT, NSETS, SPLIT);
    knn_part<<<grid1, QT>>>(x);

    knn_merge<<<NQ / 128, 128>>>(out);
}

// round 9
// speedup vs baseline: 1.7185x; 1.6636x over previous
#include <cuda_runtime.h>

#define NSETS 8
#define NPTS  4096
#define DF    16
#define KK    16
#define QT    128                 // queries per block == threads per block
#define CT    128                 // candidate tile size
#define SPLIT 4                   // candidate-range splits (occupancy lever)
#define CPS   (NPTS / SPLIT)      // candidates per split = 1024
#define NQ    (NSETS * NPTS)      // total queries = 32768
#define BUFN  20                  // per-thread append buffer slots (16 + 4 slack)

typedef unsigned long long u64;
typedef unsigned int u32;

// ---- device scratch for partial top-k (no allocs allowed) ----
__device__ float g_partD[NQ * SPLIT * KK];
__device__ int   g_partI[NQ * SPLIT * KK];

// ---- packed f32x2 helpers (two fp32 lanes per instruction, exact) ----
__device__ __forceinline__ u64 f2mul(u64 a, u64 b) {
    u64 d; asm("mul.rn.f32x2 %0, %1, %2;" : "=l"(d) : "l"(a), "l"(b)); return d;
}
__device__ __forceinline__ u64 f2fma(u64 a, u64 b, u64 c) {
    u64 d; asm("fma.rn.f32x2 %0, %1, %2, %3;" : "=l"(d) : "l"(a), "l"(b), "l"(c)); return d;
}
__device__ __forceinline__ u64 f2add(u64 a, u64 b) {
    u64 d; asm("add.rn.f32x2 %0, %1, %2;" : "=l"(d) : "l"(a), "l"(b)); return d;
}

// 16-dim dot with a FIXED summation tree, used for norms AND cross dots so
// that self-distance cancels exactly: dot(q,q)==qn => fmaf(-2,dot,qn+cn)==0.
__device__ __forceinline__ float pdot16(const u64* a, const u64* b) {
    u64 pA = f2mul(a[0], b[0]);
    pA = f2fma(a[1], b[1], pA);
    pA = f2fma(a[2], b[2], pA);
    pA = f2fma(a[3], b[3], pA);
    u64 pB = f2mul(a[4], b[4]);
    pB = f2fma(a[5], b[5], pB);
    pB = f2fma(a[6], b[6], pB);
    pB = f2fma(a[7], b[7], pB);
    u64 pC = f2add(pA, pB);
    float lo, hi;
    asm("mov.b64 {%0, %1}, %2;" : "=f"(lo), "=f"(hi) : "l"(pC));
    return lo + hi;
}

// ============================ pass 1: partial top-k ============================
__global__ __launch_bounds__(QT) void knn_part(const float* __restrict__ x) {
    __shared__ ulonglong2 sC[CT * 4];     // candidate tile: 4x ulonglong2 per point
    __shared__ float      sN[CT];         // candidate squared norms
    __shared__ u64        sBuf[BUFN][QT]; // per-thread append buffers (conflict-free)

    const int set   = blockIdx.y;
    const int split = blockIdx.z;
    const int qi    = blockIdx.x * QT + threadIdx.x;
    const float* xs = x + (size_t)set * NPTS * DF;

    // query point (packed) + its norm
    u64 q[8];
    {
        const ulonglong2* qp = reinterpret_cast<const ulonglong2*>(xs + (size_t)qi * DF);
        ulonglong2 w0 = qp[0], w1 = qp[1], w2 = qp[2], w3 = qp[3];
        q[0] = w0.x; q[1] = w0.y; q[2] = w1.x; q[3] = w1.y;
        q[4] = w2.x; q[5] = w2.y; q[6] = w3.x; q[7] = w3.y;
    }
    const float qn = pdot16(q, q);

    float bestD[KK];
    int   bestI[KK];
#pragma unroll
    for (int t = 0; t < KK; ++t) {
        bestD[t] = __int_as_float(0x7f800000);  // +inf
        bestI[t] = 0;
    }
    float threshD = __int_as_float(0x7f800000);
    int cnt = 0;

    // drain this thread's buffer into its sorted top-k (rare, warp-batched)
    auto flush = [&]() {
        for (int b = 0; b < cnt; ++b) {
            u64 key = sBuf[b][threadIdx.x];
            u32 iu; float d;
            asm("mov.b64 {%0, %1}, %2;" : "=r"(iu), "=f"(d) : "l"(key));
            if (d < bestD[KK - 1]) {   // re-check vs current (tighter) threshold
                const int idx = (int)iu;
#pragma unroll
                for (int t = KK - 1; t >= 1; --t) {
                    const bool shift = d < bestD[t - 1];
                    const bool here  = d < bestD[t];
                    bestD[t] = shift ? bestD[t - 1] : (here ? d : bestD[t]);
                    bestI[t] = shift ? bestI[t - 1] : (here ? idx : bestI[t]);
                }
                if (d < bestD[0]) { bestD[0] = d; bestI[0] = idx; }
            }
        }
        cnt = 0;
        threshD = bestD[KK - 1];
    };

    const int cbase = split * CPS;
    for (int tile = 0; tile < CPS / CT; ++tile) {
        const int cj0 = cbase + tile * CT;
        __syncthreads();
        {
            const ulonglong2* cp = reinterpret_cast<const ulonglong2*>(
                xs + (size_t)(cj0 + threadIdx.x) * DF);
            ulonglong2 w0 = cp[0], w1 = cp[1], w2 = cp[2], w3 = cp[3];
            sC[threadIdx.x * 4 + 0] = w0;
            sC[threadIdx.x * 4 + 1] = w1;
            sC[threadIdx.x * 4 + 2] = w2;
            sC[threadIdx.x * 4 + 3] = w3;
            u64 a[8] = {w0.x, w0.y, w1.x, w1.y, w2.x, w2.y, w3.x, w3.y};
            sN[threadIdx.x] = pdot16(a, a);
        }
        __syncthreads();

        for (int j0 = 0; j0 < CT; j0 += 4) {
#pragma unroll
            for (int u = 0; u < 4; ++u) {
                const int j = j0 + u;
                const ulonglong2* sp = &sC[j * 4];
                ulonglong2 w0 = sp[0], w1 = sp[1], w2 = sp[2], w3 = sp[3];
                u64 c[8] = {w0.x, w0.y, w1.x, w1.y, w2.x, w2.y, w3.x, w3.y};
                const float dot = pdot16(q, c);
                const float d = fmaf(-2.0f, dot, qn + sN[j]);
                const int idx = cj0 + j;
                u64 key;
                asm("mov.b64 %0, {%1, %2};" : "=l"(key) : "r"(idx), "f"(d));
                // branch-free conditional append: unconditional store to slot
                // cnt (garbage overwritten before cnt passes it), predicated inc
                sBuf[cnt][threadIdx.x] = key;
                cnt += (d < threshD) ? 1 : 0;
            }
            // warp-uniform check every 4 candidates (4 slots of buffer slack)
            if (__any_sync(0xffffffffu, cnt >= KK)) flush();
        }
    }
    if (__any_sync(0xffffffffu, cnt > 0)) flush();

    // write sorted partial list
    const int q_glob = set * NPTS + qi;
    float4* pd = reinterpret_cast<float4*>(&g_partD[((size_t)q_glob * SPLIT + split) * KK]);
    int4*   pi = reinterpret_cast<int4*>(&g_partI[((size_t)q_glob * SPLIT + split) * KK]);
#pragma unroll
    for (int t = 0; t < KK; t += 4) {
        pd[t / 4] = make_float4(bestD[t], bestD[t + 1], bestD[t + 2], bestD[t + 3]);
        pi[t / 4] = make_int4(bestI[t], bestI[t + 1], bestI[t + 2], bestI[t + 3]);
    }
}

// ============================ pass 2: merge + emit ============================
__device__ __forceinline__ bool lex_less(float d1, int i1, float d2, int i2) {
    return (d1 < d2) || (d1 == d2 && i1 < i2);
}

// merge two sorted-ascending 16-lists, keep the 16 smallest, result sorted.
__device__ __forceinline__ void merge16(const float* dA, const int* iA,
                                        const float* dB, const int* iB,
                                        float* dR, int* iR) {
#pragma unroll
    for (int i = 0; i < KK; ++i) {
        const bool ta = lex_less(dA[i], iA[i], dB[KK - 1 - i], iB[KK - 1 - i]);
        dR[i] = ta ? dA[i] : dB[KK - 1 - i];
        iR[i] = ta ? iA[i] : iB[KK - 1 - i];
    }
#pragma unroll
    for (int s = 8; s >= 1; s >>= 1) {
#pragma unroll
        for (int i = 0; i < KK; ++i) {
            if ((i & s) == 0) {
                const bool swap = !lex_less(dR[i], iR[i], dR[i + s], iR[i + s]);
                const float td = swap ? dR[i + s] : dR[i];
                const int   ti = swap ? iR[i + s] : iR[i];
                dR[i + s] = swap ? dR[i] : dR[i + s];
                iR[i + s] = swap ? iR[i] : iR[i + s];
                dR[i] = td;
                iR[i] = ti;
            }
        }
    }
}

__global__ __launch_bounds__(128) void knn_merge(float* __restrict__ out) {
    const int q = blockIdx.x * 128 + threadIdx.x;  // global query id
    if (q >= NQ) return;

    float D[SPLIT][KK];
    int   I[SPLIT][KK];
#pragma unroll
    for (int s = 0; s < SPLIT; ++s) {
        const float4* pd = reinterpret_cast<const float4*>(&g_partD[((size_t)q * SPLIT + s) * KK]);
        const int4*   pi = reinterpret_cast<const int4*>(&g_partI[((size_t)q * SPLIT + s) * KK]);
#pragma unroll
        for (int t = 0; t < KK / 4; ++t) {
            float4 v = pd[t];
            int4   w = pi[t];
            D[s][t * 4 + 0] = v.x; D[s][t * 4 + 1] = v.y;
            D[s][t * 4 + 2] = v.z; D[s][t * 4 + 3] = v.w;
            I[s][t * 4 + 0] = w.x; I[s][t * 4 + 1] = w.y;
            I[s][t * 4 + 2] = w.z; I[s][t * 4 + 3] = w.w;
        }
    }

    float m01[KK], m23[KK], fin[KK];
    int   j01[KK], j23[KK], jin[KK];
    merge16(D[0], I[0], D[1], I[1], m01, j01);
    merge16(D[2], I[2], D[3], I[3], m23, j23);
    merge16(m01, j01, m23, j23, fin, jin);

    const int set  = q / NPTS;
    const int base = set * NPTS;
    const size_t stride = (size_t)NQ * KK;

    float4* o_src = reinterpret_cast<float4*>(out + (size_t)q * KK);
    float4* o_dst = reinterpret_cast<float4*>(out + stride + (size_t)q * KK);
    float4* o_dis = reinterpret_cast<float4*>(out + 2 * stride + (size_t)q * KK);

    const float sv = (float)q;
#pragma unroll
    for (int t = 0; t < KK; t += 4) {
        o_src[t / 4] = make_float4(sv, sv, sv, sv);
        o_dst[t / 4] = make_float4((float)(base + jin[t + 0]),
                                   (float)(base + jin[t + 1]),
                                   (float)(base + jin[t + 2]),
                                   (float)(base + jin[t + 3]));
        o_dis[t / 4] = make_float4(fin[t + 0], fin[t + 1], fin[t + 2], fin[t + 3]);
    }
}

extern "C" void kernel_launch(void* const* d_in, const int* in_sizes, int n_in,
                              void* d_out, int out_size) {
    const float* x = (const float*)d_in[0];
    float* out = (float*)d_out;

    dim3 grid1(NPTS / QT, NSETS, SPLIT);
    knn_part<<<grid1, QT>>>(x);

    knn_merge<<<NQ / 128, 128>>>(out);
}